// round 3
// baseline (speedup 1.0000x reference)
#include <cuda_runtime.h>
#include <cstdint>

// out[t, :] = W[:, w[t]] + b   for 32768 tokens, W 8192x8192 fp32.
//
// Pipeline:
//  1) hist_kernel  (16 blocks): per-block private histogram of token indices.
//  2) scan_kernel  (1 block)  : totals -> exclusive scan -> g_offset; also
//                               per-(block,bin) cursor bases into g_part.
//  3) sort_kernel  (16 blocks): counting-sort tokens by index into g_pack
//                               using smem cursors (no global atomics).
//  4) scatter_kernel (256x32 blocks): load W[n0:n0+256, i0:i0+32] coalesced
//     (each W line read ONCE chip-wide), transpose into XOR-swizzled smem,
//     then for each token in this column group write out[t, n0:n0+256]
//     = column + bias via 2x LDS.128 + 2x STG.128 per lane (1KB/token/block).
// DRAM: 0.25 GiB read (W) + 1 GiB write (out) ~= floor.

#define N_LOC 8192
#define N_TOK 32768
#define G 32                 // columns (indices) per group
#define R 256                // rows per chunk
#define NG (N_LOC / G)       // 256
#define NC (N_LOC / R)       // 32
#define NB 16                // prep blocks
#define TOK_PER_B (N_TOK / NB)   // 2048

__device__ int g_offset[N_LOC + 1];      // exclusive scan of histogram
__device__ int g_part[NB][N_LOC];        // per-block counts, then cursor bases
__device__ unsigned g_pack[N_TOK];       // tokens sorted by index: (i<<17)|t

// Detect index dtype from the first 2048 tokens' words (safe for both
// dtypes). int64: every high word is 0 (values < 8192). int32: odd words are
// real indices, nonzero with overwhelming probability. Returns true if int64.
__device__ __forceinline__ bool detect_is64(const unsigned* wraw, int tid,
                                            int nthreads, unsigned* sh_or) {
    if (tid == 0) *sh_or = 0u;
    __syncthreads();
    unsigned acc = 0u;
    for (int m = tid; m < 2048; m += nthreads) acc |= wraw[2 * m + 1];
#pragma unroll
    for (int o = 16; o; o >>= 1) acc |= __shfl_xor_sync(~0u, acc, o);
    if ((tid & 31) == 0) atomicOr(sh_or, acc);
    __syncthreads();
    return (*sh_or == 0u);
}

// ---------------------------------------------------------------------------
__global__ void __launch_bounds__(1024) hist_kernel(const unsigned* __restrict__ wraw) {
    __shared__ int sh_cnt[N_LOC];
    __shared__ unsigned sh_or;
    const int tid = threadIdx.x;
    const int b = blockIdx.x;
    for (int j = tid; j < N_LOC; j += 1024) sh_cnt[j] = 0;
    const bool is64 = detect_is64(wraw, tid, 1024, &sh_or);  // includes syncs
    __syncthreads();
    const int t0 = b * TOK_PER_B;
    for (int t = t0 + tid; t < t0 + TOK_PER_B; t += 1024) {
        int i = is64 ? (int)((const long long*)wraw)[t] : ((const int*)wraw)[t];
        atomicAdd(&sh_cnt[i], 1);
    }
    __syncthreads();
    for (int j = tid; j < N_LOC; j += 1024) g_part[b][j] = sh_cnt[j];
}

// ---------------------------------------------------------------------------
__global__ void __launch_bounds__(1024) scan_kernel() {
    __shared__ int sh_warp[32];
    const int tid = threadIdx.x;
    const int lane = tid & 31, wid = tid >> 5;
    const int base = tid * 8;

    // totals for my 8 bins
    int v[8]; int tot = 0;
#pragma unroll
    for (int m = 0; m < 8; m++) {
        int s = 0;
#pragma unroll
        for (int b = 0; b < NB; b++) s += g_part[b][base + m];
        v[m] = s; tot += s;
    }
    // block-wide exclusive scan of per-thread totals
    int s = tot;
#pragma unroll
    for (int o = 1; o < 32; o <<= 1) {
        int x = __shfl_up_sync(~0u, s, o);
        if (lane >= o) s += x;
    }
    if (lane == 31) sh_warp[wid] = s;
    __syncthreads();
    if (wid == 0) {
        int t2 = sh_warp[lane];
        int s2 = t2;
#pragma unroll
        for (int o = 1; o < 32; o <<= 1) {
            int x = __shfl_up_sync(~0u, s2, o);
            if (lane >= o) s2 += x;
        }
        sh_warp[lane] = s2 - t2;
    }
    __syncthreads();
    int run = sh_warp[wid] + (s - tot);
    // per-bin offsets + per-(block,bin) cursor bases
#pragma unroll
    for (int m = 0; m < 8; m++) {
        int i = base + m;
        g_offset[i] = run;
        int cur = run;
#pragma unroll
        for (int b = 0; b < NB; b++) {
            int c = g_part[b][i];
            g_part[b][i] = cur;
            cur += c;
        }
        run += v[m];
    }
    if (tid == 1023) g_offset[N_LOC] = run;
}

// ---------------------------------------------------------------------------
__global__ void __launch_bounds__(1024) sort_kernel(const unsigned* __restrict__ wraw) {
    __shared__ int sh_cur[N_LOC];
    __shared__ unsigned sh_or;
    const int tid = threadIdx.x;
    const int b = blockIdx.x;
    for (int j = tid; j < N_LOC; j += 1024) sh_cur[j] = g_part[b][j];
    const bool is64 = detect_is64(wraw, tid, 1024, &sh_or);
    __syncthreads();
    const int t0 = b * TOK_PER_B;
    for (int t = t0 + tid; t < t0 + TOK_PER_B; t += 1024) {
        int i = is64 ? (int)((const long long*)wraw)[t] : ((const int*)wraw)[t];
        int pos = atomicAdd(&sh_cur[i], 1);
        g_pack[pos] = ((unsigned)i << 17) | (unsigned)t;
    }
}

// ---------------------------------------------------------------------------
// Swizzled tile: physical float4-group = logical_group ^ (c>>2).
// Transpose-store phase and LDS.128 read phase are both conflict-free.
// ---------------------------------------------------------------------------
__global__ void __launch_bounds__(256) scatter_kernel(
    const float* __restrict__ W,
    const float* __restrict__ bias,
    float* __restrict__ out)
{
    __shared__ float4 tile4[G * (R / 4)];        // 32 x 64 float4 = 32 KB
    float* tile = (float*)tile4;
    const int g     = blockIdx.x;                // column group
    const int chunk = blockIdx.y;                // row chunk
    const int i0 = g * G;
    const int n0 = chunk * R;
    const int tid = threadIdx.x;
    const int lane = tid & 31, wid = tid >> 5;

    // Load W[n0:n0+R, i0:i0+G]: 2048 float4, 8 per thread, coalesced 128B/row.
    const float4* __restrict__ Wv =
        (const float4*)(W + (size_t)n0 * N_LOC + i0);
#pragma unroll
    for (int k = 0; k < 8; k++) {
        int fid = tid + k * 256;                 // 0..2047
        int r = fid >> 3;                        // row 0..255
        int q = fid & 7;                         // float4 within row = c>>2
        float4 v = __ldcs(&Wv[(size_t)r * (N_LOC / 4) + q]);
        int sw = (((r >> 2) ^ q) << 2) + (r & 3);
        tile[(4 * q + 0) * R + sw] = v.x;
        tile[(4 * q + 1) * R + sw] = v.y;
        tile[(4 * q + 2) * R + sw] = v.z;
        tile[(4 * q + 3) * R + sw] = v.w;
    }

    // bias for this warp's lanes: floats n0 + 4*lane + {0..3} + 128h
    const float4* __restrict__ bias4 = (const float4*)bias;
    float4 bv0 = __ldg(&bias4[n0 / 4 + lane]);
    float4 bv1 = __ldg(&bias4[n0 / 4 + 32 + lane]);
    __syncthreads();

    const int start = g_offset[i0];
    const int end   = g_offset[i0 + G];
    float4* __restrict__ out4 = (float4*)out;

    for (int j = start + wid; j < end; j += 8) {
        unsigned p = __ldg(&g_pack[j]);          // broadcast
        int t = (int)(p & 0x1FFFFu);
        int c = (int)(p >> 17) - i0;
        int qc = c >> 2;
        const float4* row = &tile4[c * (R / 4)];
        float4 a = row[lane ^ qc];               // logical group = lane
        float4 b2 = row[(lane + 32) ^ qc];       // logical group = lane+32
        a.x += bv0.x; a.y += bv0.y; a.z += bv0.z; a.w += bv0.w;
        b2.x += bv1.x; b2.y += bv1.y; b2.z += bv1.z; b2.w += bv1.w;
        size_t o = (size_t)t * (N_LOC / 4) + n0 / 4;
        __stcs(&out4[o + lane], a);
        __stcs(&out4[o + 32 + lane], b2);
    }
}

extern "C" void kernel_launch(void* const* d_in, const int* in_sizes, int n_in,
                              void* d_out, int out_size) {
    const void*  w_idx = d_in[0];                 // [512,64] int32 or int64
    const float* W     = (const float*)d_in[1];   // [8192, 8192]
    const float* b     = (const float*)d_in[2];   // [8192]
    float*       out   = (float*)d_out;           // [32768, 8192]

    hist_kernel<<<NB, 1024>>>((const unsigned*)w_idx);
    scan_kernel<<<1, 1024>>>();
    sort_kernel<<<NB, 1024>>>((const unsigned*)w_idx);

    dim3 grid(NG, NC);
    scatter_kernel<<<grid, 256>>>(W, b, out);
}

// round 4
// speedup vs baseline: 1.3923x; 1.3923x over previous
#include <cuda_runtime.h>
#include <cstdint>

// out[t, :] = W[:, w[t]] + b   for 32768 tokens, W 8192x8192 fp32.
//
// Prep (cheap, multi-SM, no single-SM LSU hotspots):
//   zero_kernel   (1 blk):  g_count = 0, detect idx dtype -> g_is64
//   hist_kernel   (16 blk): global atomicAdd over 8192 bins (spread REDG)
//   scan_kernel   (1 blk):  vectorized load of 8192 counts, exclusive scan
//                           -> g_offset, g_cursor
//   sort_kernel   (16 blk): counting-sort via global atomic cursors -> g_pack
// Scatter (DRAM-bound, ~1.26 GB total traffic):
//   grid (256 col-groups x 16 row-chunks). Block loads W[n0:n0+512, i0:i0+32]
//   coalesced (each W line read ONCE chip-wide), transposes into XOR-swizzled
//   64KB smem, then writes out[t, n0:n0+512] = column + bias as one 2KB
//   contiguous burst per token (4x LDS.128 + 4x STG.128 per lane).

#define N_LOC 8192
#define N_TOK 32768
#define G 32                 // columns (indices) per group
#define R 512                // rows per chunk
#define NG (N_LOC / G)       // 256
#define NC (N_LOC / R)       // 16
#define NB 16                // prep blocks
#define TOK_PER_B (N_TOK / NB)   // 2048
#define SMEM_BYTES (G * R * 4)   // 65536

__device__ int g_count[N_LOC];
__device__ int g_offset[N_LOC + 1];
__device__ int g_cursor[N_LOC];
__device__ unsigned g_pack[N_TOK];   // (i << 17) | t
__device__ int g_is64;

// ---------------------------------------------------------------------------
// Zero counts + detect index dtype. int64: values < 8192 so every high word
// is 0. int32: odd words are real indices, nonzero with overwhelming prob.
// ---------------------------------------------------------------------------
__global__ void __launch_bounds__(1024) zero_kernel(const unsigned* __restrict__ wraw) {
    __shared__ unsigned sh_or;
    const int tid = threadIdx.x;
    if (tid == 0) sh_or = 0u;
    for (int j = tid; j < N_LOC; j += 1024) g_count[j] = 0;
    __syncthreads();
    unsigned acc = 0u;
    for (int m = tid; m < 2048; m += 1024) acc |= wraw[2 * m + 1];
#pragma unroll
    for (int o = 16; o; o >>= 1) acc |= __shfl_xor_sync(~0u, acc, o);
    if ((tid & 31) == 0) atomicOr(&sh_or, acc);
    __syncthreads();
    if (tid == 0) g_is64 = (sh_or == 0u) ? 1 : 0;
}

__device__ __forceinline__ int load_idx(const void* wraw, int t, int is64) {
    return is64 ? (int)((const long long*)wraw)[t] : ((const int*)wraw)[t];
}

// ---------------------------------------------------------------------------
__global__ void __launch_bounds__(1024) hist_kernel(const void* __restrict__ wraw) {
    const int is64 = g_is64;
    const int t0 = blockIdx.x * TOK_PER_B;
    for (int t = t0 + threadIdx.x; t < t0 + TOK_PER_B; t += 1024) {
        atomicAdd(&g_count[load_idx(wraw, t, is64)], 1);
    }
}

// ---------------------------------------------------------------------------
__global__ void __launch_bounds__(1024) scan_kernel() {
    __shared__ int sh_warp[32];
    const int tid = threadIdx.x;
    const int lane = tid & 31, wid = tid >> 5;
    const int base = tid * 8;

    int4 a = ((const int4*)g_count)[tid * 2];
    int4 c = ((const int4*)g_count)[tid * 2 + 1];
    int v[8] = {a.x, a.y, a.z, a.w, c.x, c.y, c.z, c.w};
    int tot = 0;
#pragma unroll
    for (int m = 0; m < 8; m++) tot += v[m];

    int s = tot;
#pragma unroll
    for (int o = 1; o < 32; o <<= 1) {
        int x = __shfl_up_sync(~0u, s, o);
        if (lane >= o) s += x;
    }
    if (lane == 31) sh_warp[wid] = s;
    __syncthreads();
    if (wid == 0) {
        int t2 = sh_warp[lane];
        int s2 = t2;
#pragma unroll
        for (int o = 1; o < 32; o <<= 1) {
            int x = __shfl_up_sync(~0u, s2, o);
            if (lane >= o) s2 += x;
        }
        sh_warp[lane] = s2 - t2;   // exclusive warp prefix
    }
    __syncthreads();
    int run = sh_warp[wid] + (s - tot);
#pragma unroll
    for (int m = 0; m < 8; m++) {
        g_offset[base + m] = run;
        g_cursor[base + m] = run;
        run += v[m];
    }
    if (tid == 1023) g_offset[N_LOC] = run;   // == N_TOK
}

// ---------------------------------------------------------------------------
__global__ void __launch_bounds__(1024) sort_kernel(const void* __restrict__ wraw) {
    const int is64 = g_is64;
    const int t0 = blockIdx.x * TOK_PER_B;
    for (int t = t0 + threadIdx.x; t < t0 + TOK_PER_B; t += 1024) {
        int i = load_idx(wraw, t, is64);
        int pos = atomicAdd(&g_cursor[i], 1);
        g_pack[pos] = ((unsigned)i << 17) | (unsigned)t;
    }
}

// ---------------------------------------------------------------------------
// Swizzled tile: physical float4-group = logical_group ^ (c>>2).
// Both the transpose-store phase (STS.32) and the LDS.128 read phase are
// bank-conflict-free (R % 32 == 0 keeps the per-column base bank-invariant).
// ---------------------------------------------------------------------------
__global__ void __launch_bounds__(256) scatter_kernel(
    const float* __restrict__ W,
    const float* __restrict__ bias,
    float* __restrict__ out)
{
    extern __shared__ float4 tile4[];            // G * R/4 float4 = 64 KB
    float* tile = (float*)tile4;
    const int g     = blockIdx.x;                // column group
    const int chunk = blockIdx.y;                // row chunk
    const int i0 = g * G;
    const int n0 = chunk * R;
    const int tid = threadIdx.x;
    const int lane = tid & 31, wid = tid >> 5;

    // Load W[n0:n0+R, i0:i0+G]: 4096 float4, 16 per thread, coalesced.
    const float4* __restrict__ Wv =
        (const float4*)(W + (size_t)n0 * N_LOC + i0);
#pragma unroll
    for (int k = 0; k < 16; k++) {
        int fid = tid + k * 256;                 // 0..4095
        int r = fid >> 3;                        // row 0..511
        int q = fid & 7;                         // float4 within row
        float4 v = __ldcs(&Wv[(size_t)r * (N_LOC / 4) + q]);
        int sw = (((r >> 2) ^ q) << 2) + (r & 3);
        tile[(4 * q + 0) * R + sw] = v.x;
        tile[(4 * q + 1) * R + sw] = v.y;
        tile[(4 * q + 2) * R + sw] = v.z;
        tile[(4 * q + 3) * R + sw] = v.w;
    }

    // bias: lane covers float4 groups lane + 32k, k = 0..3
    const float4* __restrict__ bias4 = (const float4*)bias;
    float4 bv[4];
#pragma unroll
    for (int k = 0; k < 4; k++) bv[k] = __ldg(&bias4[n0 / 4 + 32 * k + lane]);
    __syncthreads();

    const int start = g_offset[i0];
    const int end   = g_offset[i0 + G];
    float4* __restrict__ out4 = (float4*)out;

    for (int j = start + wid; j < end; j += 8) {
        unsigned p = __ldg(&g_pack[j]);          // broadcast
        int t = (int)(p & 0x1FFFFu);
        int qc = (int)(p >> 17) - i0;            // column in group
        const float4* row = &tile4[qc * (R / 4)];
        const int x = qc >> 2;
        size_t o = (size_t)t * (N_LOC / 4) + n0 / 4;
#pragma unroll
        for (int k = 0; k < 4; k++) {
            float4 v = row[(lane + 32 * k) ^ x];
            v.x += bv[k].x; v.y += bv[k].y; v.z += bv[k].z; v.w += bv[k].w;
            __stcs(&out4[o + 32 * k + lane], v);
        }
    }
}

extern "C" void kernel_launch(void* const* d_in, const int* in_sizes, int n_in,
                              void* d_out, int out_size) {
    const void*  w_idx = d_in[0];                 // [512,64] int32 or int64
    const float* W     = (const float*)d_in[1];   // [8192, 8192]
    const float* b     = (const float*)d_in[2];   // [8192]
    float*       out   = (float*)d_out;           // [32768, 8192]

    static bool attr_done = false;
    if (!attr_done) {
        cudaFuncSetAttribute(scatter_kernel,
                             cudaFuncAttributeMaxDynamicSharedMemorySize,
                             SMEM_BYTES);
        attr_done = true;
    }

    zero_kernel<<<1, 1024>>>((const unsigned*)w_idx);
    hist_kernel<<<NB, 1024>>>(w_idx);
    scan_kernel<<<1, 1024>>>();
    sort_kernel<<<NB, 1024>>>(w_idx);

    dim3 grid(NG, NC);
    scatter_kernel<<<grid, 256, SMEM_BYTES>>>(W, b, out);
}